// round 7
// baseline (speedup 1.0000x reference)
#include <cuda_runtime.h>

#define BB 4
#define CC 64
#define HH 512
#define WW 512
#define HWSZ (HH * WW)            // 262144
#define NPIX (BB * HWSZ)          // 1048576
#define NQUAD (NPIX / 4)          // 262144
#define N_ORI 20
#define NBLOCKS (NQUAD / 256)     // 1024
#define STAGES 4
#define IGN 255

// Scratch (allocation-free per harness rules). Statically zeroed for first
// run; the last block of each run resets them, keeping graph replays
// deterministic.
__device__ double g_sum = 0.0;
__device__ unsigned long long g_cnt = 0ull;
__device__ unsigned int g_ticket = 0u;

__device__ __forceinline__ void cp_async16(unsigned int saddr, const void* gptr) {
    asm volatile("cp.async.cg.shared.global [%0], [%1], 16;\n"
                 :: "r"(saddr), "l"(gptr) : "memory");
}
__device__ __forceinline__ void cp_commit() {
    asm volatile("cp.async.commit_group;\n" ::: "memory");
}
template <int N>
__device__ __forceinline__ void cp_wait() {
    asm volatile("cp.async.wait_group %0;\n" :: "n"(N) : "memory");
}

__global__ __launch_bounds__(256, 7) void uce_kernel(
    const float* __restrict__ inp,   // [B, C, H, W] f32
    const int* __restrict__ tgt,     // [B, H, W] int32
    const int* __restrict__ gid,     // [C] int32
    float* __restrict__ out)
{
    __shared__ __align__(16) float4 sbuf[STAGES * 256];   // 16 KB ring
    __shared__ int sgid[CC];

    int tid = threadIdx.x;
    if (tid < CC) sgid[tid] = gid[tid];
    __syncthreads();

    int q = blockIdx.x * 256 + tid;          // quad index (4 pixels/thread)
    int p  = q << 2;
    int b  = p >> 18;                        // p / HWSZ
    int hw = p & (HWSZ - 1);                 // multiple of 4 -> float4 aligned
    const float* base = inp + (size_t)b * (CC * HWSZ) + hw;

    // This thread's slot in stage 0 (stage s = +s*4096 bytes)
    unsigned int slot0 = (unsigned int)__cvta_generic_to_shared(&sbuf[tid]);

    // Prologue: fill all stages (channels 0..STAGES-1)
    #pragma unroll
    for (int s = 0; s < STAGES; ++s) {
        cp_async16(slot0 + s * 4096, base + (size_t)s * HWSZ);
        cp_commit();
    }

    int4 t = *reinterpret_cast<const int4*>(tgt + p);

    float a0 = 0.f, a1 = 0.f, a2 = 0.f, a3 = 0.f;   // all-channel sums
    float s0 = 0.f, s1 = 0.f, s2 = 0.f, s3 = 0.f;   // target-group sums

    #pragma unroll 8
    for (int c = 0; c < CC; ++c) {
        cp_wait<STAGES - 1>();                       // oldest stage (channel c) ready
        int slot = (c & (STAGES - 1));               // compile-time under unroll 8
        float4 v = sbuf[slot * 256 + tid];           // self-consume, no barrier
        int g = sgid[c];                             // broadcast LDS

        float e0 = __expf(v.x), e1 = __expf(v.y);
        float e2 = __expf(v.z), e3 = __expf(v.w);
        a0 += e0; a1 += e1; a2 += e2; a3 += e3;
        if (g == t.x) s0 += e0;
        if (g == t.y) s1 += e1;
        if (g == t.z) s2 += e2;
        if (g == t.w) s3 += e3;

        int nc = c + STAGES;
        if (nc < CC)
            cp_async16(slot0 + slot * 4096, base + (size_t)nc * HWSZ);
        cp_commit();                                 // empty groups in the tail are fine
    }

    // Validity: targets outside [0, N_ORI) (incl. ignore=255) never matched ->
    // s stays 0; guard before log.
    bool v0 = (unsigned)t.x < N_ORI;
    bool v1 = (unsigned)t.y < N_ORI;
    bool v2 = (unsigned)t.z < N_ORI;
    bool v3 = (unsigned)t.w < N_ORI;

    float lsum = 0.0f;
    int   lcnt = 0;
    // -(log(s_t) - log(s_all)) = log(s_all) - log(s_t)
    if (v0) { lsum += __logf(a0) - __logf(s0); lcnt++; }
    if (v1) { lsum += __logf(a1) - __logf(s1); lcnt++; }
    if (v2) { lsum += __logf(a2) - __logf(s2); lcnt++; }
    if (v3) { lsum += __logf(a3) - __logf(s3); lcnt++; }

    // Warp reduce
    #pragma unroll
    for (int o = 16; o > 0; o >>= 1) {
        lsum += __shfl_down_sync(0xFFFFFFFFu, lsum, o);
        lcnt += __shfl_down_sync(0xFFFFFFFFu, lcnt, o);
    }

    __shared__ float wsum[8];
    __shared__ int   wcnt[8];
    int wid = tid >> 5;
    int lid = tid & 31;
    if (lid == 0) { wsum[wid] = lsum; wcnt[wid] = lcnt; }
    __syncthreads();

    __shared__ bool s_last;
    if (tid == 0) {
        float bs = 0.f; int bc = 0;
        #pragma unroll
        for (int w = 0; w < 8; ++w) { bs += wsum[w]; bc += wcnt[w]; }
        atomicAdd(&g_sum, (double)bs);
        atomicAdd(&g_cnt, (unsigned long long)bc);
        __threadfence();
        unsigned int ticket = atomicAdd(&g_ticket, 1u);
        s_last = (ticket == NBLOCKS - 1);
    }
    __syncthreads();

    if (s_last && tid == 0) {
        double sum = atomicAdd(&g_sum, 0.0);                    // acquire-read
        unsigned long long n = atomicAdd(&g_cnt, 0ull);
        if (n < 1ull) n = 1ull;
        out[0] = (float)(sum / (double)n);
        // Reset scratch for the next graph replay (deterministic).
        g_sum = 0.0;
        g_cnt = 0ull;
        __threadfence();
        g_ticket = 0u;
    }
}

extern "C" void kernel_launch(void* const* d_in, const int* in_sizes, int n_in,
                              void* d_out, int out_size) {
    const float* inp = (const float*)d_in[0];
    const int*   tgt = (const int*)d_in[1];
    const int*   gid = (const int*)d_in[2];
    float*       out = (float*)d_out;

    uce_kernel<<<NBLOCKS, 256>>>(inp, tgt, gid, out);
}